// round 5
// baseline (speedup 1.0000x reference)
#include <cuda_runtime.h>
#include <cuda_bf16.h>

#define N_NODES 50000
#define E_CAP   700000
#define HEADS   4
#define OUT_CH  16
#define OUT_NEU 32
#define IN_CH   128
#define HID     128   // HEADS*OUT_NEU

// ---- output layout (flat concat of reference return tuple, fp32) ----
#define OFF_OUT    0
#define OFF_IXZ    (N_NODES * 64)                  // 3,200,000
#define OFF_SCALAR (OFF_IXZ + N_NODES)             // 3,250,000
#define OFF_MEAN   (OFF_SCALAR + 1)                // 3,250,001 (ODD -> no vector stores!)
#define OFF_STD    (OFF_MEAN + N_NODES * 64)       // 6,450,001 (ODD -> no vector stores!)

// ---- scratch (device globals; no allocation allowed) ----
__device__ __align__(16) float g_h[N_NODES * HID];     // node features after GEMM
__device__ __align__(16) float g_aI[N_NODES * HEADS];  // h . att_i (dst term)
__device__ __align__(16) float g_aJ[N_NODES * HEADS];  // h . att_j (src term)
__device__ int g_deg[N_NODES];
__device__ int g_start[N_NODES + 1];
__device__ int g_cursor[N_NODES];
__device__ int g_csr_src[E_CAP];

// ---------------------------------------------------------------- K0: zero deg
__global__ void zero_deg_kernel() {
    int i = blockIdx.x * blockDim.x + threadIdx.x;
    if (i < N_NODES) g_deg[i] = 0;
}

// ---------------------------------------------------------------- K1: histogram
__global__ void hist_kernel(const int* __restrict__ dst, int E) {
    int e = blockIdx.x * blockDim.x + threadIdx.x;
    if (e < E) atomicAdd(&g_deg[dst[e]], 1);
}

// ---------------------------------------------------------------- K2: scan (1 block)
__global__ __launch_bounds__(1024) void scan_kernel() {
    __shared__ int warpsum[32];
    const int T = 1024;
    const int CH = (N_NODES + T - 1) / T;   // 49
    int t = threadIdx.x;
    int lo = t * CH;
    int hi = lo + CH; if (hi > N_NODES) hi = N_NODES;

    int s = 0;
    for (int i = lo; i < hi; i++) s += g_deg[i];

    int lane = t & 31, wid = t >> 5;
    int v = s;
#pragma unroll
    for (int o = 1; o < 32; o <<= 1) {
        int nv = __shfl_up_sync(0xffffffffu, v, o);
        if (lane >= o) v += nv;
    }
    if (lane == 31) warpsum[wid] = v;
    __syncthreads();
    if (wid == 0) {
        int w = warpsum[lane];
#pragma unroll
        for (int o = 1; o < 32; o <<= 1) {
            int nw = __shfl_up_sync(0xffffffffu, w, o);
            if (lane >= o) w += nw;
        }
        warpsum[lane] = w;
    }
    __syncthreads();

    int excl = v - s + (wid ? warpsum[wid - 1] : 0);
    int run = excl;
    for (int i = lo; i < hi; i++) {
        int d = g_deg[i];
        g_start[i]  = run;
        g_cursor[i] = run;
        run += d;
    }
    if (t == T - 1) g_start[N_NODES] = run;
}

// ---------------------------------------------------------------- K3: scatter
__global__ void scatter_kernel(const int* __restrict__ src,
                               const int* __restrict__ dst, int E) {
    int e = blockIdx.x * blockDim.x + threadIdx.x;
    if (e >= E) return;
    int pos = atomicAdd(&g_cursor[dst[e]], 1);
    g_csr_src[pos] = src[e];
}

// ------------------------------------------- K4: GEMM + per-node attention dots
#define GEMM_ROWS 16
#define XT_PITCH  20
#define GEMM_SMEM ((IN_CH * HID + IN_CH * XT_PITCH) * 4)

__global__ __launch_bounds__(256) void gemm_kernel(
    const float* __restrict__ x, const float* __restrict__ w,
    const float* __restrict__ att)
{
    extern __shared__ float sm[];
    float* sW  = sm;                 // [k][col]
    float* sXT = sm + IN_CH * HID;   // [k][row] pitch 20

    const int tid  = threadIdx.x;
    const int row0 = blockIdx.x * GEMM_ROWS;

    for (int i = tid; i < IN_CH * HID; i += 256) sW[i] = w[i];
    for (int i = tid; i < GEMM_ROWS * IN_CH; i += 256) {
        int r = i >> 7, k = i & 127;
        sXT[k * XT_PITCH + r] = x[(row0 + r) * IN_CH + k];
    }
    __syncthreads();

    const int col = tid & 127;
    const int rh  = tid >> 7;      // 0 or 1

    float acc[8];
#pragma unroll
    for (int j = 0; j < 8; j++) acc[j] = 0.0f;

#pragma unroll 4
    for (int k = 0; k < IN_CH; k++) {
        const float wv = sW[k * HID + col];
        const float4 a0 = *(const float4*)&sXT[k * XT_PITCH + rh * 8];
        const float4 a1 = *(const float4*)&sXT[k * XT_PITCH + rh * 8 + 4];
        acc[0] = fmaf(a0.x, wv, acc[0]);
        acc[1] = fmaf(a0.y, wv, acc[1]);
        acc[2] = fmaf(a0.z, wv, acc[2]);
        acc[3] = fmaf(a0.w, wv, acc[3]);
        acc[4] = fmaf(a1.x, wv, acc[4]);
        acc[5] = fmaf(a1.y, wv, acc[5]);
        acc[6] = fmaf(a1.z, wv, acc[6]);
        acc[7] = fmaf(a1.w, wv, acc[7]);
    }

    const int head = col >> 5;
    const int lane = col & 31;
    const float attI = att[head * 64 + lane];
    const float attJ = att[head * 64 + 32 + lane];

#pragma unroll
    for (int j = 0; j < 8; j++) {
        const int row = row0 + rh * 8 + j;
        g_h[row * HID + col] = acc[j];
        float sI = acc[j] * attI;
        float sJ = acc[j] * attJ;
#pragma unroll
        for (int o = 16; o; o >>= 1) {
            sI += __shfl_xor_sync(0xffffffffu, sI, o);
            sJ += __shfl_xor_sync(0xffffffffu, sJ, o);
        }
        if (lane == 0) {
            g_aI[row * HEADS + head] = sI;
            g_aJ[row * HEADS + head] = sJ;
        }
    }
}

// ------------- K5: warp-per-node SINGLE-PASS softmax-aggregation + VIB epilogue
// inv = 1/(den+eps) is a per-node constant, so accumulate unnormalized
// acc = sum_j e_j * h[src_j] and den = sum_j e_j in ONE loop; scale at the end.
// Each lane walks all edges serially -> its den (for its head) is complete
// without any reduction. src index for j+1 is prefetched to overlap latency.
__global__ __launch_bounds__(256) void node_kernel(
    const float* __restrict__ bias, float* __restrict__ out)
{
    const int warp = threadIdx.x >> 5, lane = threadIdx.x & 31;
    const int n = blockIdx.x * 8 + warp;
    if (n >= N_NODES) return;

    const int beg = g_start[n], end = g_start[n + 1];
    const int head = lane >> 3;            // lane owns channels [lane*4, lane*4+4)
    const float aIh = __ldg(&g_aI[n * 4 + head]);

    float4 acc = make_float4(0.f, 0.f, 0.f, 0.f);
    float den = 0.f;

    int s_cur = (beg < end) ? __ldg(&g_csr_src[beg]) : 0;
    for (int j = beg; j < end; j++) {
        // prefetch next src index (overlaps this iteration's dependent loads)
        const int s_nxt = (j + 1 < end) ? __ldg(&g_csr_src[j + 1]) : 0;

        const float ajv = __ldg(&g_aJ[s_cur * 4 + head]);
        const float4 hv = *(const float4*)&g_h[s_cur * HID + lane * 4];

        float a = aIh + ajv;
        a = a > 0.f ? a : 0.2f * a;
        const float e = expf(a);
        den += e;
        acc.x = fmaf(hv.x, e, acc.x);
        acc.y = fmaf(hv.y, e, acc.y);
        acc.z = fmaf(hv.z, e, acc.z);
        acc.w = fmaf(hv.w, e, acc.w);

        s_cur = s_nxt;
    }

    const float inv = 1.0f / (den + 1e-16f);
    acc.x *= inv; acc.y *= inv; acc.z *= inv; acc.w *= inv;

    // ---- VIB epilogue on register accumulator ----
    const float4 b4 = *(const float4*)&bias[lane * 4];
    const int cc = lane & 7;
    float kl;
    if (cc < 4) {
        float4 m;
        m.x = acc.x + b4.x; m.y = acc.y + b4.y;
        m.z = acc.z + b4.z; m.w = acc.w + b4.w;
        const int o1 = n * 64 + head * 16 + cc * 4;
        *(float4*)&out[OFF_OUT + o1] = m;           // OFF_OUT region is 16B aligned
        out[OFF_MEAN + o1 + 0] = m.x;
        out[OFF_MEAN + o1 + 1] = m.y;
        out[OFF_MEAN + o1 + 2] = m.z;
        out[OFF_MEAN + o1 + 3] = m.w;
        kl = 0.5f * (m.x * m.x + m.y * m.y + m.z * m.z + m.w * m.w);
    } else {
        float4 sp;
        sp.x = acc.x + b4.x - 5.0f; sp.y = acc.y + b4.y - 5.0f;
        sp.z = acc.z + b4.z - 5.0f; sp.w = acc.w + b4.w - 5.0f;
        float4 st;
        st.x = fmaxf(sp.x, 0.f) + log1pf(expf(-fabsf(sp.x))) + 1e-10f;
        st.y = fmaxf(sp.y, 0.f) + log1pf(expf(-fabsf(sp.y))) + 1e-10f;
        st.z = fmaxf(sp.z, 0.f) + log1pf(expf(-fabsf(sp.z))) + 1e-10f;
        st.w = fmaxf(sp.w, 0.f) + log1pf(expf(-fabsf(sp.w))) + 1e-10f;
        const int o2 = n * 64 + head * 16 + (cc - 4) * 4;
        out[OFF_STD + o2 + 0] = st.x;
        out[OFF_STD + o2 + 1] = st.y;
        out[OFF_STD + o2 + 2] = st.z;
        out[OFF_STD + o2 + 3] = st.w;
        kl = (-logf(st.x) + 0.5f * st.x * st.x - 0.5f)
           + (-logf(st.y) + 0.5f * st.y * st.y - 0.5f)
           + (-logf(st.z) + 0.5f * st.z * st.z - 0.5f)
           + (-logf(st.w) + 0.5f * st.w * st.w - 0.5f);
    }
#pragma unroll
    for (int o = 16; o; o >>= 1) kl += __shfl_xor_sync(0xffffffffu, kl, o);
    if (lane == 0) out[OFF_IXZ + n] = kl * 0.25f;
    if (blockIdx.x == 0 && threadIdx.x == 0) out[OFF_SCALAR] = 0.0f;
}

// ---------------------------------------------------------------- launch
extern "C" void kernel_launch(void* const* d_in, const int* in_sizes, int n_in,
                              void* d_out, int out_size)
{
    const float* x    = (const float*)d_in[0];
    const int*   ei   = (const int*)d_in[1];
    const float* w    = (const float*)d_in[2];
    const float* att  = (const float*)d_in[3];
    const float* bias = (const float*)d_in[4];
    float* out = (float*)d_out;

    const int E = in_sizes[1] / 2;
    const int* src = ei;
    const int* dst = ei + E;

    cudaFuncSetAttribute(gemm_kernel,
                         cudaFuncAttributeMaxDynamicSharedMemorySize, GEMM_SMEM);

    const int eb = (E + 255) / 256;
    zero_deg_kernel<<<(N_NODES + 511) / 512, 512>>>();
    hist_kernel<<<eb, 256>>>(dst, E);
    scan_kernel<<<1, 1024>>>();
    scatter_kernel<<<eb, 256>>>(src, dst, E);
    gemm_kernel<<<N_NODES / GEMM_ROWS, 256, GEMM_SMEM>>>(x, w, att);
    node_kernel<<<(N_NODES + 7) / 8, 256>>>(bias, out);
}

// round 6
// speedup vs baseline: 1.2158x; 1.2158x over previous
#include <cuda_runtime.h>
#include <cuda_bf16.h>

#define N_NODES 50000
#define E_CAP   700000
#define HEADS   4
#define OUT_CH  16
#define OUT_NEU 32
#define IN_CH   128
#define HID     128   // HEADS*OUT_NEU

// ---- output layout (flat concat of reference return tuple, fp32) ----
#define OFF_OUT    0
#define OFF_IXZ    (N_NODES * 64)                  // 3,200,000
#define OFF_SCALAR (OFF_IXZ + N_NODES)             // 3,250,000
#define OFF_MEAN   (OFF_SCALAR + 1)                // 3,250,001 (ODD -> no vector stores!)
#define OFF_STD    (OFF_MEAN + N_NODES * 64)       // 6,450,001 (ODD -> no vector stores!)

// ---- scratch (device globals; no allocation allowed) ----
__device__ __align__(16) float g_h[N_NODES * HID];     // node features after GEMM
__device__ __align__(16) float g_agg[N_NODES * HID];   // segment-sum accumulator
__device__ __align__(16) float g_aI[N_NODES * HEADS];  // h . att_i (dst term)
__device__ __align__(16) float g_aJ[N_NODES * HEADS];  // h . att_j (src term)
__device__ __align__(16) float g_denom[N_NODES * HEADS]; // denom, then 1/(denom+eps)

__device__ __forceinline__ void red_add_v4(float* gptr, float a, float b, float c, float d) {
    asm volatile("red.global.add.v4.f32 [%0], {%1, %2, %3, %4};"
                 :: "l"(gptr), "f"(a), "f"(b), "f"(c), "f"(d) : "memory");
}

__device__ __forceinline__ float lrelu(float a) {
    return a > 0.0f ? a : 0.2f * a;
}

// ---------------------------------------------------------------- K0: init
__global__ void init_kernel() {
    int i = blockIdx.x * blockDim.x + threadIdx.x;
    int stride = gridDim.x * blockDim.x;
    float4 z = make_float4(0.f, 0.f, 0.f, 0.f);
    for (int k = i; k < N_NODES * HID / 4; k += stride)
        ((float4*)g_agg)[k] = z;
    for (int k = i; k < N_NODES; k += stride)
        ((float4*)g_denom)[k] = z;
}

// ------------------------------------------- K1: GEMM + per-node attention dots
#define GEMM_ROWS 16
#define XT_PITCH  20
#define GEMM_SMEM ((IN_CH * HID + IN_CH * XT_PITCH) * 4)

__global__ __launch_bounds__(256) void gemm_kernel(
    const float* __restrict__ x, const float* __restrict__ w,
    const float* __restrict__ att)
{
    extern __shared__ float sm[];
    float* sW  = sm;                 // [k][col]
    float* sXT = sm + IN_CH * HID;   // [k][row] pitch 20

    const int tid  = threadIdx.x;
    const int row0 = blockIdx.x * GEMM_ROWS;

    for (int i = tid; i < IN_CH * HID; i += 256) sW[i] = w[i];
    for (int i = tid; i < GEMM_ROWS * IN_CH; i += 256) {
        int r = i >> 7, k = i & 127;
        sXT[k * XT_PITCH + r] = x[(row0 + r) * IN_CH + k];
    }
    __syncthreads();

    const int col = tid & 127;
    const int rh  = tid >> 7;      // 0 or 1

    float acc[8];
#pragma unroll
    for (int j = 0; j < 8; j++) acc[j] = 0.0f;

#pragma unroll 4
    for (int k = 0; k < IN_CH; k++) {
        const float wv = sW[k * HID + col];
        const float4 a0 = *(const float4*)&sXT[k * XT_PITCH + rh * 8];
        const float4 a1 = *(const float4*)&sXT[k * XT_PITCH + rh * 8 + 4];
        acc[0] = fmaf(a0.x, wv, acc[0]);
        acc[1] = fmaf(a0.y, wv, acc[1]);
        acc[2] = fmaf(a0.z, wv, acc[2]);
        acc[3] = fmaf(a0.w, wv, acc[3]);
        acc[4] = fmaf(a1.x, wv, acc[4]);
        acc[5] = fmaf(a1.y, wv, acc[5]);
        acc[6] = fmaf(a1.z, wv, acc[6]);
        acc[7] = fmaf(a1.w, wv, acc[7]);
    }

    const int head = col >> 5;
    const int lane = col & 31;
    const float attI = att[head * 64 + lane];
    const float attJ = att[head * 64 + 32 + lane];

#pragma unroll
    for (int j = 0; j < 8; j++) {
        const int row = row0 + rh * 8 + j;
        g_h[row * HID + col] = acc[j];
        float sI = acc[j] * attI;
        float sJ = acc[j] * attJ;
#pragma unroll
        for (int o = 16; o; o >>= 1) {
            sI += __shfl_xor_sync(0xffffffffu, sI, o);
            sJ += __shfl_xor_sync(0xffffffffu, sJ, o);
        }
        if (lane == 0) {
            g_aI[row * HEADS + head] = sI;
            g_aJ[row * HEADS + head] = sJ;
        }
    }
}

// ------------------- K2: per-edge e = exp(leaky(aI[d]+aJ[s])); denom[d] += e
// No max subtraction: e/(denom+eps) is scale invariant (validated R4/R5).
__global__ void edge_denom(const int* __restrict__ src,
                           const int* __restrict__ dst, int E)
{
    int e = blockIdx.x * blockDim.x + threadIdx.x;
    if (e >= E) return;
    int s = src[e], d = dst[e];
    const float4 ai = *(const float4*)&g_aI[d * 4];
    const float4 aj = *(const float4*)&g_aJ[s * 4];
    float ex = __expf(lrelu(ai.x + aj.x));
    float ey = __expf(lrelu(ai.y + aj.y));
    float ez = __expf(lrelu(ai.z + aj.z));
    float ew = __expf(lrelu(ai.w + aj.w));
    red_add_v4(&g_denom[d * 4], ex, ey, ez, ew);
}

// ------------------- K3: denom -> 1/(denom + eps)  (in place)
__global__ void inv_kernel() {
    int n = blockIdx.x * blockDim.x + threadIdx.x;
    if (n >= N_NODES) return;
    float4 d = ((const float4*)g_denom)[n];
    d.x = 1.0f / (d.x + 1e-16f);
    d.y = 1.0f / (d.y + 1e-16f);
    d.z = 1.0f / (d.z + 1e-16f);
    d.w = 1.0f / (d.w + 1e-16f);
    ((float4*)g_denom)[n] = d;
}

// ------------------- K4: agg[dst] += h[src] * e * inv[dst]
// 32 threads per edge; lane -> (head = lane>>3, float4-chunk = lane&7)
__global__ void edge_agg(const int* __restrict__ src,
                         const int* __restrict__ dst, int E)
{
    int g = blockIdx.x * blockDim.x + threadIdx.x;
    int e = g >> 5;
    if (e >= E) return;
    int lane = g & 31;
    int s = src[e], d = dst[e];
    int head = lane >> 3;
    float aih = __ldg(&g_aI[d * 4 + head]);   // broadcast within 8-lane group
    float ajh = __ldg(&g_aJ[s * 4 + head]);
    float inv = __ldg(&g_denom[d * 4 + head]);
    float coef = __expf(lrelu(aih + ajh)) * inv;
    float4 hv = ((const float4*)g_h)[s * 32 + lane];  // lane*4 == head*32 + q*4
    red_add_v4(&g_agg[d * HID + lane * 4],
               hv.x * coef, hv.y * coef, hv.z * coef, hv.w * coef);
}

// ----------------------------------- K5: VIB epilogue + all outputs
// warp per node: lane -> (head = lane>>3, cc = lane&7 handles c=cc and c=cc+8)
__global__ __launch_bounds__(256) void finalize_kernel(
    const float* __restrict__ bias, float* __restrict__ out)
{
    int warp = threadIdx.x >> 5, lane = threadIdx.x & 31;
    int n = blockIdx.x * 8 + warp;
    if (n >= N_NODES) return;
    int head = lane >> 3, cc = lane & 7;

    float kl = 0.0f;
#pragma unroll
    for (int t = 0; t < 2; t++) {
        int c = cc + t * 8;
        float mv = g_agg[n * HID + head * 32 + c] + bias[head * 32 + c];
        float sp = g_agg[n * HID + head * 32 + 16 + c] + bias[head * 32 + 16 + c] - 5.0f;
        // stable softplus: max(x,0) + log1p(exp(-|x|))
        float st = fmaxf(sp, 0.0f) + log1pf(expf(-fabsf(sp))) + 1e-10f;
        kl += -logf(st) + 0.5f * (st * st + mv * mv) - 0.5f;
        out[OFF_OUT  + n * 64 + head * 16 + c] = mv;
        out[OFF_MEAN + n * 64 + head * 16 + c] = mv;
        out[OFF_STD  + n * 64 + head * 16 + c] = st;
    }
#pragma unroll
    for (int o = 16; o; o >>= 1) kl += __shfl_xor_sync(0xffffffffu, kl, o);
    if (lane == 0) out[OFF_IXZ + n] = kl * 0.25f;
    if (blockIdx.x == 0 && threadIdx.x == 0) out[OFF_SCALAR] = 0.0f;
}

// ---------------------------------------------------------------- launch
extern "C" void kernel_launch(void* const* d_in, const int* in_sizes, int n_in,
                              void* d_out, int out_size)
{
    const float* x    = (const float*)d_in[0];
    const int*   ei   = (const int*)d_in[1];
    const float* w    = (const float*)d_in[2];
    const float* att  = (const float*)d_in[3];
    const float* bias = (const float*)d_in[4];
    float* out = (float*)d_out;

    const int E = in_sizes[1] / 2;
    const int* src = ei;
    const int* dst = ei + E;

    cudaFuncSetAttribute(gemm_kernel,
                         cudaFuncAttributeMaxDynamicSharedMemorySize, GEMM_SMEM);

    init_kernel<<<512, 256>>>();
    gemm_kernel<<<N_NODES / GEMM_ROWS, 256, GEMM_SMEM>>>(x, w, att);

    const int eb = (E + 255) / 256;
    edge_denom<<<eb, 256>>>(src, dst, E);
    inv_kernel<<<(N_NODES + 255) / 256, 256>>>();
    edge_agg<<<(E * 32 + 255) / 256, 256>>>(src, dst, E);
    finalize_kernel<<<(N_NODES + 7) / 8, 256>>>(bias, out);
}